// round 8
// baseline (speedup 1.0000x reference)
#include <cuda_runtime.h>
#include <cuda_bf16.h>
#include <cstdint>

#define NN  100000
#define NE  500000
#define H   128
#define D_U 256
#define D_I 300
#define NUH (NN * H)
#define SCAN_NB 98            // ceil(NN/1024)

// ---------------- scratch (static device globals; no allocation) -------------
__device__ float g_hu[2][NUH];
__device__ float g_hi[2][NUH];
__device__ float g_deg[6][NN];     // rsqrt: 0 out_uu, 1 in_uu, 2 out_ui, 3 in_ui, 4 out_iu, 5 in_iu
__device__ int   g_degi[6][NN];    // int degrees (same layout)
__device__ int   g_off[3][NN];     // CSR row starts per etype: 0=uu, 1=ui, 2=iu
__device__ int   g_cur[3][NN];     // fill cursors
__device__ int   g_esrc[3][NE];    // edge src sorted by dst
__device__ int   g_bsum[3][128];   // scan block sums

// ---------------- small helpers ----------------------------------------------
__device__ __forceinline__ uint32_t smem_u32(const void* p) {
    uint32_t a;
    asm("{ .reg .u64 t; cvta.to.shared.u64 t, %1; cvt.u32.u64 %0, t; }" : "=r"(a) : "l"(p));
    return a;
}
__device__ __forceinline__ void ldm_x4(uint32_t* r, uint32_t addr) {
    asm volatile("ldmatrix.sync.aligned.m8n8.x4.shared.b16 {%0,%1,%2,%3}, [%4];"
                 : "=r"(r[0]), "=r"(r[1]), "=r"(r[2]), "=r"(r[3]) : "r"(addr));
}
__device__ __forceinline__ void ldm_x4_t(uint32_t* r, uint32_t addr) {
    asm volatile("ldmatrix.sync.aligned.m8n8.x4.trans.shared.b16 {%0,%1,%2,%3}, [%4];"
                 : "=r"(r[0]), "=r"(r[1]), "=r"(r[2]), "=r"(r[3]) : "r"(addr));
}
__device__ __forceinline__ void mma_bf16(float* d, const uint32_t* a, uint32_t b0, uint32_t b1) {
    asm volatile("mma.sync.aligned.m16n8k16.row.col.f32.bf16.bf16.f32 "
                 "{%0,%1,%2,%3}, {%4,%5,%6,%7}, {%8,%9}, {%0,%1,%2,%3};"
                 : "+f"(d[0]), "+f"(d[1]), "+f"(d[2]), "+f"(d[3])
                 : "r"(a[0]), "r"(a[1]), "r"(a[2]), "r"(a[3]), "r"(b0), "r"(b1));
}
__device__ __forceinline__ void split2(float a, float b, uint32_t& hi, float& ra, float& rb) {
    __nv_bfloat16 ha = __float2bfloat16(a), hb = __float2bfloat16(b);
    hi = (uint32_t)__bfloat16_as_ushort(ha) | ((uint32_t)__bfloat16_as_ushort(hb) << 16);
    ra = a - __bfloat162float(ha);
    rb = b - __bfloat162float(hb);
}
__device__ __forceinline__ uint32_t pack2(float a, float b) {
    return (uint32_t)__bfloat16_as_ushort(__float2bfloat16(a)) |
           ((uint32_t)__bfloat16_as_ushort(__float2bfloat16(b)) << 16);
}

// ---------------- setup kernels ----------------------------------------------
__global__ void zero_int_kernel(int* p, int n) {
    int i = blockIdx.x * blockDim.x + threadIdx.x;
    int stride = gridDim.x * blockDim.x;
    for (; i < n; i += stride) p[i] = 0;
}

__global__ void deg_count_kernel(const int* __restrict__ suu, const int* __restrict__ duu,
                                 const int* __restrict__ sui, const int* __restrict__ dui,
                                 const int* __restrict__ siu, const int* __restrict__ diu,
                                 int* __restrict__ degi) {
    int i = blockIdx.x * blockDim.x + threadIdx.x;
    if (i >= NE) return;
    atomicAdd(&degi[0 * NN + suu[i]], 1);
    atomicAdd(&degi[1 * NN + duu[i]], 1);
    atomicAdd(&degi[2 * NN + sui[i]], 1);
    atomicAdd(&degi[3 * NN + dui[i]], 1);
    atomicAdd(&degi[4 * NN + siu[i]], 1);
    atomicAdd(&degi[5 * NN + diu[i]], 1);
}

__global__ void deg_finalize_kernel(const int* __restrict__ degi, float* __restrict__ deg) {
    int i = blockIdx.x * blockDim.x + threadIdx.x;
    if (i >= NN) return;
#pragma unroll
    for (int j = 0; j < 6; j++)
        deg[j * NN + i] = rsqrtf(fmaxf((float)degi[j * NN + i], 1.f));
}

// block scan over in-degrees (rows 1,3,5 of degi) -> per-block exclusive prefix
__global__ void scan_s1(const int* __restrict__ degi, int* __restrict__ off,
                        int* __restrict__ bsum) {
    int et = blockIdx.y;
    const int* d = degi + (1 + 2 * et) * NN;
    int* o = off + et * NN;
    __shared__ int wsum[8], woff[8];
    int t = threadIdx.x;
    int base = blockIdx.x * 1024 + t * 4;
    int x[4];
#pragma unroll
    for (int j = 0; j < 4; j++) x[j] = (base + j < NN) ? d[base + j] : 0;
    int tl = x[0] + x[1] + x[2] + x[3];
    int incl = tl;
#pragma unroll
    for (int s = 1; s < 32; s <<= 1) {
        int y = __shfl_up_sync(0xffffffff, incl, s);
        if ((t & 31) >= s) incl += y;
    }
    if ((t & 31) == 31) wsum[t >> 5] = incl;
    __syncthreads();
    if (t == 0) {
        int a = 0;
#pragma unroll
        for (int k = 0; k < 8; k++) { woff[k] = a; a += wsum[k]; }
    }
    __syncthreads();
    int run = woff[t >> 5] + incl - tl;
#pragma unroll
    for (int j = 0; j < 4; j++) {
        if (base + j < NN) o[base + j] = run;
        run += x[j];
    }
    if (t == 255) bsum[et * 128 + blockIdx.x] = woff[7] + wsum[7];
}

__global__ void scan_s2(int* bsum) {
    int et = threadIdx.x;
    if (et < 3) {
        int a = 0;
        for (int i = 0; i < SCAN_NB; i++) {
            int t = bsum[et * 128 + i];
            bsum[et * 128 + i] = a;
            a += t;
        }
    }
}

__global__ void scan_s3(int* __restrict__ off, const int* __restrict__ bsum) {
    int et = blockIdx.y;
    int i = blockIdx.x * blockDim.x + threadIdx.x;
    if (i < NN) off[et * NN + i] += bsum[et * 128 + (i >> 10)];
}

__global__ void fill_kernel(const int* __restrict__ src, const int* __restrict__ dst,
                            const int* __restrict__ off, int* __restrict__ cur,
                            int* __restrict__ esrc) {
    int e = blockIdx.x * blockDim.x + threadIdx.x;
    if (e >= NE) return;
    int d = dst[e];
    int p = atomicAdd(&cur[d], 1);
    esrc[off[d] + p] = src[e];
}

// ---------------- bf16x3-split tensor-core GEMM (dense or CSR-gather A) ------
// dense (off==nullptr): C = epi( A[M,K] @ W[K,128] )
// CSR:   A[row][:] = sum_{e in csr row} X[esrc[e]][:] * rout[esrc[e]]   (K=128)
// epi(x) = maybe_relu(x * rs[row] + bias[col]);  accum: C += epi(...)
#define ABUF 10240
#define BBUF 8192
#define BUFSZ (2 * ABUF + 2 * BBUF)
#define SM_BIAS (2 * BUFSZ)
#define TCSMEM (SM_BIAS + 512)

__global__ __launch_bounds__(256, 2) void mma_gemm_kernel(
    const float* __restrict__ A, const float* __restrict__ W,
    const float* __restrict__ bias, const float* __restrict__ rowscale,
    const int* __restrict__ off, const int* __restrict__ esrc,
    const float* __restrict__ rout,
    float* __restrict__ C, int M, int K, int doRelu, int accum)
{
    extern __shared__ char sm[];
    const uint32_t sbase = smem_u32(sm);
    const int tid = threadIdx.x, lane = tid & 31, wid = tid >> 5;
    const int blockRow = blockIdx.x * 128;
    const int wm = (wid & 3) * 32;
    const int wn = (wid >> 2) * 64;
    const bool csr = (off != nullptr);

    if (tid < 128) ((float*)(sm + SM_BIAS))[tid] = bias[tid];

    float acc[2][8][4];
#pragma unroll
    for (int i = 0; i < 2; i++)
#pragma unroll
        for (int j = 0; j < 8; j++)
#pragma unroll
            for (int k = 0; k < 4; k++) acc[i][j][k] = 0.f;

    const int nch = (K + 31) / 32;

    const int r8 = lane & 7, sel = lane >> 3;
    const int a_row = r8 + ((sel & 1) << 3);
    const int a_kb  = (sel >> 1) << 4;
    const int b_csel = sel >> 1;

    auto load_chunk = [&](int ch) {
        const int k0 = ch * 32;
        char* buf = sm + (ch & 1) * BUFSZ;
        // A tile: 128 rows x 32 k (dense load or CSR gather)
#pragma unroll
        for (int i = 0; i < 4; i++) {
            int idx = tid + i * 256;
            int row = idx >> 3, q = idx & 7;
            int gm = blockRow + row, gk = k0 + q * 4;
            float4 v = make_float4(0.f, 0.f, 0.f, 0.f);
            if (gm < M) {
                if (csr) {
                    int b = __ldg(&off[gm]);
                    int en = (gm + 1 < M) ? __ldg(&off[gm + 1]) : NE;
                    for (int j = b; j < en; j++) {
                        int s = __ldg(&esrc[j]);
                        float r = __ldg(&rout[s]);
                        float4 xv = *(const float4*)(A + (size_t)s * H + gk);
                        v.x += xv.x * r; v.y += xv.y * r;
                        v.z += xv.z * r; v.w += xv.w * r;
                    }
                } else {
                    const float* ap = A + (size_t)gm * K + gk;
                    if (gk + 3 < K) v = *(const float4*)ap;
                    else {
                        if (gk + 0 < K) v.x = ap[0];
                        if (gk + 1 < K) v.y = ap[1];
                        if (gk + 2 < K) v.z = ap[2];
                        if (gk + 3 < K) v.w = ap[3];
                    }
                }
            }
            float rx, ry, rz, rw;
            uint2 hi, lo;
            split2(v.x, v.y, hi.x, rx, ry);
            split2(v.z, v.w, hi.y, rz, rw);
            lo.x = pack2(rx, ry);
            lo.y = pack2(rz, rw);
            *(uint2*)(buf + (size_t)row * 80 + q * 8) = hi;
            *(uint2*)(buf + ABUF + (size_t)row * 80 + q * 8) = lo;
        }
        // B tile: 32 k-rows x 128 n, XOR chunk swizzle
#pragma unroll
        for (int i = 0; i < 4; i++) {
            int idx = tid + i * 256;
            int kk = idx >> 5, q = idx & 31;
            int gk = k0 + kk;
            float4 v = make_float4(0.f, 0.f, 0.f, 0.f);
            if (gk < K) v = *(const float4*)(W + (size_t)gk * 128 + q * 4);
            float rx, ry, rz, rw;
            uint2 hi, lo;
            split2(v.x, v.y, hi.x, rx, ry);
            split2(v.z, v.w, hi.y, rz, rw);
            lo.x = pack2(rx, ry);
            lo.y = pack2(rz, rw);
            uint32_t o = (uint32_t)kk * 256 + ((((uint32_t)(q >> 1)) ^ (kk & 7)) << 4) + (q & 1) * 8;
            *(uint2*)(buf + 2 * ABUF + o) = hi;
            *(uint2*)(buf + 2 * ABUF + BBUF + o) = lo;
        }
    };

    load_chunk(0);
    __syncthreads();

    for (int ch = 0; ch < nch; ch++) {
        if (ch + 1 < nch) load_chunk(ch + 1);
        const uint32_t bufb = sbase + (ch & 1) * BUFSZ;

#pragma unroll
        for (int h = 0; h < 2; h++) {
            uint32_t ah[2][4], al[2][4], bf[4][4];
#pragma unroll
            for (int mt = 0; mt < 2; mt++) {
                uint32_t arow = wm + mt * 16 + a_row;
                uint32_t aaddr = bufb + arow * 80 + h * 32 + a_kb;
                ldm_x4(ah[mt], aaddr);
                ldm_x4(al[mt], aaddr + ABUF);
            }
            const int kk = h * 16 + a_row;
            const uint32_t brow = bufb + 2 * ABUF + (uint32_t)kk * 256;
#pragma unroll
            for (int j = 0; j < 4; j++) {
                uint32_t chunk = (uint32_t)((wn >> 3) + j * 2 + b_csel) ^ (kk & 7);
                ldm_x4_t(bf[j], brow + chunk * 16);
            }
#pragma unroll
            for (int j = 0; j < 4; j++)
#pragma unroll
                for (int mt = 0; mt < 2; mt++) {
                    mma_bf16(acc[mt][2 * j],     ah[mt], bf[j][0], bf[j][1]);
                    mma_bf16(acc[mt][2 * j + 1], ah[mt], bf[j][2], bf[j][3]);
                    mma_bf16(acc[mt][2 * j],     al[mt], bf[j][0], bf[j][1]);
                    mma_bf16(acc[mt][2 * j + 1], al[mt], bf[j][2], bf[j][3]);
                }
#pragma unroll
            for (int j = 0; j < 4; j++) {
                uint32_t chunk = (uint32_t)((wn >> 3) + j * 2 + b_csel) ^ (kk & 7);
                ldm_x4_t(bf[j], brow + BBUF + chunk * 16);
            }
#pragma unroll
            for (int j = 0; j < 4; j++)
#pragma unroll
                for (int mt = 0; mt < 2; mt++) {
                    mma_bf16(acc[mt][2 * j],     ah[mt], bf[j][0], bf[j][1]);
                    mma_bf16(acc[mt][2 * j + 1], ah[mt], bf[j][2], bf[j][3]);
                }
        }
        __syncthreads();
    }

    // epilogue
    const float* bs = (const float*)(sm + SM_BIAS);
    const int g = lane >> 2;
    const int t2 = (lane & 3) * 2;
#pragma unroll
    for (int mt = 0; mt < 2; mt++) {
        int row0 = blockRow + wm + mt * 16 + g;
#pragma unroll
        for (int half = 0; half < 2; half++) {
            int row = row0 + half * 8;
            if (row >= M) continue;
            float rv = rowscale ? __ldg(&rowscale[row]) : 1.f;
            float* cp = C + (size_t)row * 128;
#pragma unroll
            for (int nt = 0; nt < 8; nt++) {
                int col = wn + nt * 8 + t2;
                float v0 = acc[mt][nt][half * 2 + 0] * rv + bs[col];
                float v1 = acc[mt][nt][half * 2 + 1] * rv + bs[col + 1];
                if (doRelu) { v0 = fmaxf(v0, 0.f); v1 = fmaxf(v1, 0.f); }
                if (accum) {
                    float2 o = *(const float2*)(cp + col);
                    v0 += o.x; v1 += o.y;
                }
                *(float2*)(cp + col) = make_float2(v0, v1);
            }
        }
    }
}

// ---------------- host orchestration -----------------------------------------
extern "C" void kernel_launch(void* const* d_in, const int* in_sizes, int n_in,
                              void* d_out, int out_size) {
    const float* feat_user = (const float*)d_in[0];
    const float* feat_item = (const float*)d_in[1];
    const int* src_uu = (const int*)d_in[2];
    const int* dst_uu = (const int*)d_in[3];
    const int* src_ui = (const int*)d_in[4];
    const int* dst_ui = (const int*)d_in[5];
    const int* src_iu = (const int*)d_in[6];
    const int* dst_iu = (const int*)d_in[7];
    const float* We_u = (const float*)d_in[8];
    const float* be_u = (const float*)d_in[9];
    const float* We_i = (const float*)d_in[10];
    const float* be_i = (const float*)d_in[11];
    const float* W[3][3];
    const float* B[3][3];
    for (int l = 0; l < 3; l++)
        for (int e = 0; e < 3; e++) {
            W[l][e] = (const float*)d_in[12 + l * 6 + e * 2];
            B[l][e] = (const float*)d_in[12 + l * 6 + e * 2 + 1];
        }

    float *hu, *hi, *deg;
    int *degi, *off, *cur, *esrc, *bsum;
    cudaGetSymbolAddress((void**)&hu, g_hu);
    cudaGetSymbolAddress((void**)&hi, g_hi);
    cudaGetSymbolAddress((void**)&deg, g_deg);
    cudaGetSymbolAddress((void**)&degi, g_degi);
    cudaGetSymbolAddress((void**)&off, g_off);
    cudaGetSymbolAddress((void**)&cur, g_cur);
    cudaGetSymbolAddress((void**)&esrc, g_esrc);
    cudaGetSymbolAddress((void**)&bsum, g_bsum);
    float* out = (float*)d_out;

    cudaFuncSetAttribute(mma_gemm_kernel,
                         cudaFuncAttributeMaxDynamicSharedMemorySize, TCSMEM);

    // ---- degree + CSR build ----
    zero_int_kernel<<<256, 256>>>(degi, 6 * NN);
    zero_int_kernel<<<256, 256>>>(cur, 3 * NN);
    deg_count_kernel<<<(NE + 255) / 256, 256>>>(src_uu, dst_uu, src_ui, dst_ui,
                                                src_iu, dst_iu, degi);
    deg_finalize_kernel<<<(NN + 255) / 256, 256>>>(degi, deg);
    {
        dim3 g1(SCAN_NB, 3);
        scan_s1<<<g1, 256>>>(degi, off, bsum);
        scan_s2<<<1, 32>>>(bsum);
        dim3 g3((NN + 255) / 256, 3);
        scan_s3<<<g3, 256>>>(off, bsum);
    }
    fill_kernel<<<(NE + 255) / 256, 256>>>(src_uu, dst_uu, off + 0 * NN, cur + 0 * NN, esrc + 0 * NE);
    fill_kernel<<<(NE + 255) / 256, 256>>>(src_ui, dst_ui, off + 1 * NN, cur + 1 * NN, esrc + 1 * NE);
    fill_kernel<<<(NE + 255) / 256, 256>>>(src_iu, dst_iu, off + 2 * NN, cur + 2 * NN, esrc + 2 * NE);

    const float* rout_uu = deg + 0 * NN;
    const float* rin_uu  = deg + 1 * NN;
    const float* rout_ui = deg + 2 * NN;
    const float* rin_ui  = deg + 3 * NN;
    const float* rout_iu = deg + 4 * NN;
    const float* rin_iu  = deg + 5 * NN;

    int grid = (NN + 127) / 128;

    // ---- embed (dense GEMM) ----
    mma_gemm_kernel<<<grid, 256, TCSMEM>>>(feat_user, We_u, be_u, nullptr,
                                           nullptr, nullptr, nullptr,
                                           hu, NN, D_U, 0, 0);
    mma_gemm_kernel<<<grid, 256, TCSMEM>>>(feat_item, We_i, be_i, nullptr,
                                           nullptr, nullptr, nullptr,
                                           hi, NN, D_I, 0, 0);

    // ---- layers: CSR-gather GEMMs ----
    int cur_pp = 0;
    for (int l = 0; l < 3; l++) {
        int relu = (l < 2) ? 1 : 0;
        float* hu_cur = hu + (size_t)cur_pp * NUH;
        float* hi_cur = hi + (size_t)cur_pp * NUH;
        float* hu_nxt = (l == 2) ? out : hu + (size_t)(1 - cur_pp) * NUH;
        float* hi_nxt = (l == 2) ? out + (size_t)NUH : hi + (size_t)(1 - cur_pp) * NUH;

        // hu_nxt = relu?( agg_uu(hu)@W_uu * rin_uu + b_uu ) + relu?( agg_iu(hi)@W_iu * rin_iu + b_iu )
        mma_gemm_kernel<<<grid, 256, TCSMEM>>>(hu_cur, W[l][0], B[l][0], rin_uu,
                                               off + 0 * NN, esrc + 0 * NE, rout_uu,
                                               hu_nxt, NN, H, relu, 0);
        mma_gemm_kernel<<<grid, 256, TCSMEM>>>(hi_cur, W[l][2], B[l][2], rin_iu,
                                               off + 2 * NN, esrc + 2 * NE, rout_iu,
                                               hu_nxt, NN, H, relu, 1);
        // hi_nxt = relu?( agg_ui(hu)@W_ui * rin_ui + b_ui )
        mma_gemm_kernel<<<grid, 256, TCSMEM>>>(hu_cur, W[l][1], B[l][1], rin_ui,
                                               off + 1 * NN, esrc + 1 * NE, rout_ui,
                                               hi_nxt, NN, H, relu, 0);
        cur_pp ^= 1;
    }
    (void)in_sizes; (void)n_in; (void)out_size;
}

// round 9
// speedup vs baseline: 1.5485x; 1.5485x over previous
#include <cuda_runtime.h>
#include <cuda_bf16.h>
#include <cstdint>

#define NN  100000
#define NE  500000
#define H   128
#define D_U 256
#define D_I 300
#define NUH (NN * H)
#define SCAN_NB 98            // ceil(NN/1024)

// ---------------- scratch (static device globals; no allocation) -------------
__device__ float g_hu[2][NUH];
__device__ float g_hi[2][NUH];
__device__ float g_S[3][NUH];      // gathered neighborhoods: 0=uu, 1=ui, 2=iu
__device__ float g_deg[6][NN];     // rsqrt: 0 out_uu, 1 in_uu, 2 out_ui, 3 in_ui, 4 out_iu, 5 in_iu
__device__ int   g_degi[6][NN];    // int degrees (same layout)
__device__ int   g_off[3][NN];     // CSR row starts per etype: 0=uu, 1=ui, 2=iu
__device__ int   g_cur[3][NN];     // fill cursors
__device__ int   g_esrc[3][NE];    // edge src sorted by dst
__device__ int   g_bsum[3][128];   // scan block sums

// ---------------- small helpers ----------------------------------------------
__device__ __forceinline__ uint32_t smem_u32(const void* p) {
    uint32_t a;
    asm("{ .reg .u64 t; cvta.to.shared.u64 t, %1; cvt.u32.u64 %0, t; }" : "=r"(a) : "l"(p));
    return a;
}
__device__ __forceinline__ void ldm_x4(uint32_t* r, uint32_t addr) {
    asm volatile("ldmatrix.sync.aligned.m8n8.x4.shared.b16 {%0,%1,%2,%3}, [%4];"
                 : "=r"(r[0]), "=r"(r[1]), "=r"(r[2]), "=r"(r[3]) : "r"(addr));
}
__device__ __forceinline__ void ldm_x4_t(uint32_t* r, uint32_t addr) {
    asm volatile("ldmatrix.sync.aligned.m8n8.x4.trans.shared.b16 {%0,%1,%2,%3}, [%4];"
                 : "=r"(r[0]), "=r"(r[1]), "=r"(r[2]), "=r"(r[3]) : "r"(addr));
}
__device__ __forceinline__ void mma_bf16(float* d, const uint32_t* a, uint32_t b0, uint32_t b1) {
    asm volatile("mma.sync.aligned.m16n8k16.row.col.f32.bf16.bf16.f32 "
                 "{%0,%1,%2,%3}, {%4,%5,%6,%7}, {%8,%9}, {%0,%1,%2,%3};"
                 : "+f"(d[0]), "+f"(d[1]), "+f"(d[2]), "+f"(d[3])
                 : "r"(a[0]), "r"(a[1]), "r"(a[2]), "r"(a[3]), "r"(b0), "r"(b1));
}
__device__ __forceinline__ void split2(float a, float b, uint32_t& hi, float& ra, float& rb) {
    __nv_bfloat16 ha = __float2bfloat16(a), hb = __float2bfloat16(b);
    hi = (uint32_t)__bfloat16_as_ushort(ha) | ((uint32_t)__bfloat16_as_ushort(hb) << 16);
    ra = a - __bfloat162float(ha);
    rb = b - __bfloat162float(hb);
}
__device__ __forceinline__ uint32_t pack2(float a, float b) {
    return (uint32_t)__bfloat16_as_ushort(__float2bfloat16(a)) |
           ((uint32_t)__bfloat16_as_ushort(__float2bfloat16(b)) << 16);
}

// ---------------- setup kernels ----------------------------------------------
__global__ void zero_int_kernel(int* p, int n) {
    int i = blockIdx.x * blockDim.x + threadIdx.x;
    int stride = gridDim.x * blockDim.x;
    for (; i < n; i += stride) p[i] = 0;
}

__global__ void deg_count_kernel(const int* __restrict__ suu, const int* __restrict__ duu,
                                 const int* __restrict__ sui, const int* __restrict__ dui,
                                 const int* __restrict__ siu, const int* __restrict__ diu,
                                 int* __restrict__ degi) {
    int i = blockIdx.x * blockDim.x + threadIdx.x;
    if (i >= NE) return;
    atomicAdd(&degi[0 * NN + suu[i]], 1);
    atomicAdd(&degi[1 * NN + duu[i]], 1);
    atomicAdd(&degi[2 * NN + sui[i]], 1);
    atomicAdd(&degi[3 * NN + dui[i]], 1);
    atomicAdd(&degi[4 * NN + siu[i]], 1);
    atomicAdd(&degi[5 * NN + diu[i]], 1);
}

__global__ void deg_finalize_kernel(const int* __restrict__ degi, float* __restrict__ deg) {
    int i = blockIdx.x * blockDim.x + threadIdx.x;
    if (i >= NN) return;
#pragma unroll
    for (int j = 0; j < 6; j++)
        deg[j * NN + i] = rsqrtf(fmaxf((float)degi[j * NN + i], 1.f));
}

// block scan over in-degrees (rows 1,3,5 of degi) -> per-block exclusive prefix
__global__ void scan_s1(const int* __restrict__ degi, int* __restrict__ off,
                        int* __restrict__ bsum) {
    int et = blockIdx.y;
    const int* d = degi + (1 + 2 * et) * NN;
    int* o = off + et * NN;
    __shared__ int wsum[8], woff[8];
    int t = threadIdx.x;
    int base = blockIdx.x * 1024 + t * 4;
    int x[4];
#pragma unroll
    for (int j = 0; j < 4; j++) x[j] = (base + j < NN) ? d[base + j] : 0;
    int tl = x[0] + x[1] + x[2] + x[3];
    int incl = tl;
#pragma unroll
    for (int s = 1; s < 32; s <<= 1) {
        int y = __shfl_up_sync(0xffffffff, incl, s);
        if ((t & 31) >= s) incl += y;
    }
    if ((t & 31) == 31) wsum[t >> 5] = incl;
    __syncthreads();
    if (t == 0) {
        int a = 0;
#pragma unroll
        for (int k = 0; k < 8; k++) { woff[k] = a; a += wsum[k]; }
    }
    __syncthreads();
    int run = woff[t >> 5] + incl - tl;
#pragma unroll
    for (int j = 0; j < 4; j++) {
        if (base + j < NN) o[base + j] = run;
        run += x[j];
    }
    if (t == 255) bsum[et * 128 + blockIdx.x] = woff[7] + wsum[7];
}

__global__ void scan_s2(int* bsum) {
    int et = threadIdx.x;
    if (et < 3) {
        int a = 0;
        for (int i = 0; i < SCAN_NB; i++) {
            int t = bsum[et * 128 + i];
            bsum[et * 128 + i] = a;
            a += t;
        }
    }
}

__global__ void scan_s3(int* __restrict__ off, const int* __restrict__ bsum) {
    int et = blockIdx.y;
    int i = blockIdx.x * blockDim.x + threadIdx.x;
    if (i < NN) off[et * NN + i] += bsum[et * 128 + (i >> 10)];
}

__global__ void fill_kernel(const int* __restrict__ src, const int* __restrict__ dst,
                            const int* __restrict__ off, int* __restrict__ cur,
                            int* __restrict__ esrc) {
    int e = blockIdx.x * blockDim.x + threadIdx.x;
    if (e >= NE) return;
    int d = dst[e];
    int p = atomicAdd(&cur[d], 1);
    esrc[off[d] + p] = src[e];
}

// ---------------- CSR row gather: S[r] = sum_edges X[src]*rout[src] ----------
// warp per dst row; no atomics, no zero pass.
__global__ __launch_bounds__(256) void gather_kernel(
    const float* __restrict__ X, const float* __restrict__ rout,
    const int* __restrict__ off, const int* __restrict__ esrc,
    float* __restrict__ S) {
    int r = blockIdx.x * 8 + (threadIdx.x >> 5);
    if (r >= NN) return;
    int lane = threadIdx.x & 31;
    int b = __ldg(&off[r]);
    int e = (r + 1 < NN) ? __ldg(&off[r + 1]) : NE;
    float4 acc = make_float4(0.f, 0.f, 0.f, 0.f);
    for (int j = b; j < e; j++) {
        int s = __ldg(&esrc[j]);
        float rr = __ldg(&rout[s]);
        float4 xv = *(const float4*)(X + (size_t)s * H + lane * 4);
        acc.x += xv.x * rr; acc.y += xv.y * rr;
        acc.z += xv.z * rr; acc.w += xv.w * rr;
    }
    *(float4*)(S + (size_t)r * H + lane * 4) = acc;
}

// ---------------- bf16x3-split tensor-core GEMM ------------------------------
// C[M,128] = epi( A[M,K] @ W[K,128] ), epi(x) = maybe_relu(x*rs[row]+bias[col])
// accum: C += epi(...)
// CTA: 64(M) x 128(N), 256 thr, 8 warps of 16x64; K chunked by 32, dbl-buffered.
#define BMROWS 64
#define ABUF 5120                  // 64 rows * 80B
#define BBUF 8192                  // 32 k-rows * 256B
#define BUFSZ (2 * ABUF + 2 * BBUF)
#define SM_BIAS (2 * BUFSZ)
#define TCSMEM (SM_BIAS + 512)

__global__ __launch_bounds__(256, 3) void mma_gemm_kernel(
    const float* __restrict__ A, const float* __restrict__ W,
    const float* __restrict__ bias, const float* __restrict__ rowscale,
    float* __restrict__ C, int M, int K, int doRelu, int accum)
{
    extern __shared__ char sm[];
    const uint32_t sbase = smem_u32(sm);
    const int tid = threadIdx.x, lane = tid & 31, wid = tid >> 5;
    const int blockRow = blockIdx.x * BMROWS;
    const int wm = (wid & 3) * 16;      // warp M offset (16-row tile)
    const int wn = (wid >> 2) * 64;     // warp N offset

    if (tid < 128) ((float*)(sm + SM_BIAS))[tid] = bias[tid];

    float acc[8][4];
#pragma unroll
    for (int j = 0; j < 8; j++)
#pragma unroll
        for (int k = 0; k < 4; k++) acc[j][k] = 0.f;

    const int nch = (K + 31) / 32;

    const int r8 = lane & 7, sel = lane >> 3;
    const int a_row = r8 + ((sel & 1) << 3);   // 0..15
    const int a_kb  = (sel >> 1) << 4;
    const int b_csel = sel >> 1;

    auto load_chunk = [&](int ch) {
        const int k0 = ch * 32;
        char* buf = sm + (ch & 1) * BUFSZ;
        // A tile: 64 rows x 32 k -> 512 float4 items, 2 per thread
#pragma unroll
        for (int i = 0; i < 2; i++) {
            int idx = tid + i * 256;
            int row = idx >> 3, q = idx & 7;
            int gm = blockRow + row, gk = k0 + q * 4;
            float4 v = make_float4(0.f, 0.f, 0.f, 0.f);
            if (gm < M) {
                const float* ap = A + (size_t)gm * K + gk;
                if (gk + 3 < K) v = *(const float4*)ap;
                else {
                    if (gk + 0 < K) v.x = ap[0];
                    if (gk + 1 < K) v.y = ap[1];
                    if (gk + 2 < K) v.z = ap[2];
                    if (gk + 3 < K) v.w = ap[3];
                }
            }
            float rx, ry, rz, rw;
            uint2 hi, lo;
            split2(v.x, v.y, hi.x, rx, ry);
            split2(v.z, v.w, hi.y, rz, rw);
            lo.x = pack2(rx, ry);
            lo.y = pack2(rz, rw);
            *(uint2*)(buf + (size_t)row * 80 + q * 8) = hi;
            *(uint2*)(buf + ABUF + (size_t)row * 80 + q * 8) = lo;
        }
        // B tile: 32 k-rows x 128 n, XOR chunk swizzle -> 1024 items, 4/thread
#pragma unroll
        for (int i = 0; i < 4; i++) {
            int idx = tid + i * 256;
            int kk = idx >> 5, q = idx & 31;
            int gk = k0 + kk;
            float4 v = make_float4(0.f, 0.f, 0.f, 0.f);
            if (gk < K) v = *(const float4*)(W + (size_t)gk * 128 + q * 4);
            float rx, ry, rz, rw;
            uint2 hi, lo;
            split2(v.x, v.y, hi.x, rx, ry);
            split2(v.z, v.w, hi.y, rz, rw);
            lo.x = pack2(rx, ry);
            lo.y = pack2(rz, rw);
            uint32_t o = (uint32_t)kk * 256 + ((((uint32_t)(q >> 1)) ^ (kk & 7)) << 4) + (q & 1) * 8;
            *(uint2*)(buf + 2 * ABUF + o) = hi;
            *(uint2*)(buf + 2 * ABUF + BBUF + o) = lo;
        }
    };

    load_chunk(0);
    __syncthreads();

    for (int ch = 0; ch < nch; ch++) {
        if (ch + 1 < nch) load_chunk(ch + 1);
        const uint32_t bufb = sbase + (ch & 1) * BUFSZ;

#pragma unroll
        for (int h = 0; h < 2; h++) {
            uint32_t ah[4], al[4], bf[4][4];
            {
                uint32_t aaddr = bufb + (wm + a_row) * 80 + h * 32 + a_kb;
                ldm_x4(ah, aaddr);
                ldm_x4(al, aaddr + ABUF);
            }
            const int kk = h * 16 + a_row;
            const uint32_t brow = bufb + 2 * ABUF + (uint32_t)kk * 256;
#pragma unroll
            for (int j = 0; j < 4; j++) {
                uint32_t chunk = (uint32_t)((wn >> 3) + j * 2 + b_csel) ^ (kk & 7);
                ldm_x4_t(bf[j], brow + chunk * 16);
            }
            // hi*hi and lo*hi
#pragma unroll
            for (int j = 0; j < 4; j++) {
                mma_bf16(acc[2 * j],     ah, bf[j][0], bf[j][1]);
                mma_bf16(acc[2 * j + 1], ah, bf[j][2], bf[j][3]);
                mma_bf16(acc[2 * j],     al, bf[j][0], bf[j][1]);
                mma_bf16(acc[2 * j + 1], al, bf[j][2], bf[j][3]);
            }
            // hi*lo
#pragma unroll
            for (int j = 0; j < 4; j++) {
                uint32_t chunk = (uint32_t)((wn >> 3) + j * 2 + b_csel) ^ (kk & 7);
                ldm_x4_t(bf[j], brow + BBUF + chunk * 16);
            }
#pragma unroll
            for (int j = 0; j < 4; j++) {
                mma_bf16(acc[2 * j],     ah, bf[j][0], bf[j][1]);
                mma_bf16(acc[2 * j + 1], ah, bf[j][2], bf[j][3]);
            }
        }
        __syncthreads();
    }

    // epilogue
    const float* bs = (const float*)(sm + SM_BIAS);
    const int g = lane >> 2;
    const int t2 = (lane & 3) * 2;
#pragma unroll
    for (int half = 0; half < 2; half++) {
        int row = blockRow + wm + g + half * 8;
        if (row >= M) continue;
        float rv = rowscale ? __ldg(&rowscale[row]) : 1.f;
        float* cp = C + (size_t)row * 128;
#pragma unroll
        for (int nt = 0; nt < 8; nt++) {
            int col = wn + nt * 8 + t2;
            float v0 = acc[nt][half * 2 + 0] * rv + bs[col];
            float v1 = acc[nt][half * 2 + 1] * rv + bs[col + 1];
            if (doRelu) { v0 = fmaxf(v0, 0.f); v1 = fmaxf(v1, 0.f); }
            if (accum) {
                float2 o = *(const float2*)(cp + col);
                v0 += o.x; v1 += o.y;
            }
            *(float2*)(cp + col) = make_float2(v0, v1);
        }
    }
}

// ---------------- host orchestration -----------------------------------------
extern "C" void kernel_launch(void* const* d_in, const int* in_sizes, int n_in,
                              void* d_out, int out_size) {
    const float* feat_user = (const float*)d_in[0];
    const float* feat_item = (const float*)d_in[1];
    const int* src_uu = (const int*)d_in[2];
    const int* dst_uu = (const int*)d_in[3];
    const int* src_ui = (const int*)d_in[4];
    const int* dst_ui = (const int*)d_in[5];
    const int* src_iu = (const int*)d_in[6];
    const int* dst_iu = (const int*)d_in[7];
    const float* We_u = (const float*)d_in[8];
    const float* be_u = (const float*)d_in[9];
    const float* We_i = (const float*)d_in[10];
    const float* be_i = (const float*)d_in[11];
    const float* W[3][3];
    const float* B[3][3];
    for (int l = 0; l < 3; l++)
        for (int e = 0; e < 3; e++) {
            W[l][e] = (const float*)d_in[12 + l * 6 + e * 2];
            B[l][e] = (const float*)d_in[12 + l * 6 + e * 2 + 1];
        }

    float *hu, *hi, *S, *deg;
    int *degi, *off, *cur, *esrc, *bsum;
    cudaGetSymbolAddress((void**)&hu, g_hu);
    cudaGetSymbolAddress((void**)&hi, g_hi);
    cudaGetSymbolAddress((void**)&S, g_S);
    cudaGetSymbolAddress((void**)&deg, g_deg);
    cudaGetSymbolAddress((void**)&degi, g_degi);
    cudaGetSymbolAddress((void**)&off, g_off);
    cudaGetSymbolAddress((void**)&cur, g_cur);
    cudaGetSymbolAddress((void**)&esrc, g_esrc);
    cudaGetSymbolAddress((void**)&bsum, g_bsum);
    float* out = (float*)d_out;

    cudaFuncSetAttribute(mma_gemm_kernel,
                         cudaFuncAttributeMaxDynamicSharedMemorySize, TCSMEM);

    // ---- degree + CSR build ----
    zero_int_kernel<<<256, 256>>>(degi, 6 * NN);
    zero_int_kernel<<<256, 256>>>(cur, 3 * NN);
    deg_count_kernel<<<(NE + 255) / 256, 256>>>(src_uu, dst_uu, src_ui, dst_ui,
                                                src_iu, dst_iu, degi);
    deg_finalize_kernel<<<(NN + 255) / 256, 256>>>(degi, deg);
    {
        dim3 g1(SCAN_NB, 3);
        scan_s1<<<g1, 256>>>(degi, off, bsum);
        scan_s2<<<1, 32>>>(bsum);
        dim3 g3((NN + 255) / 256, 3);
        scan_s3<<<g3, 256>>>(off, bsum);
    }
    fill_kernel<<<(NE + 255) / 256, 256>>>(src_uu, dst_uu, off + 0 * NN, cur + 0 * NN, esrc + 0 * NE);
    fill_kernel<<<(NE + 255) / 256, 256>>>(src_ui, dst_ui, off + 1 * NN, cur + 1 * NN, esrc + 1 * NE);
    fill_kernel<<<(NE + 255) / 256, 256>>>(src_iu, dst_iu, off + 2 * NN, cur + 2 * NN, esrc + 2 * NE);

    const float* rout_uu = deg + 0 * NN;
    const float* rin_uu  = deg + 1 * NN;
    const float* rout_ui = deg + 2 * NN;
    const float* rin_ui  = deg + 3 * NN;
    const float* rout_iu = deg + 4 * NN;
    const float* rin_iu  = deg + 5 * NN;

    int grid = (NN + BMROWS - 1) / BMROWS;
    int ggrid = (NN + 7) / 8;

    // ---- embed (dense GEMM) ----
    mma_gemm_kernel<<<grid, 256, TCSMEM>>>(feat_user, We_u, be_u, nullptr,
                                           hu, NN, D_U, 0, 0);
    mma_gemm_kernel<<<grid, 256, TCSMEM>>>(feat_item, We_i, be_i, nullptr,
                                           hi, NN, D_I, 0, 0);

    // ---- layers: CSR gather + dense GEMMs ----
    int cur_pp = 0;
    for (int l = 0; l < 3; l++) {
        int relu = (l < 2) ? 1 : 0;
        float* hu_cur = hu + (size_t)cur_pp * NUH;
        float* hi_cur = hi + (size_t)cur_pp * NUH;
        float* hu_nxt = (l == 2) ? out : hu + (size_t)(1 - cur_pp) * NUH;
        float* hi_nxt = (l == 2) ? out + (size_t)NUH : hi + (size_t)(1 - cur_pp) * NUH;
        float* Suu = S + 0 * (size_t)NUH;
        float* Sui = S + 1 * (size_t)NUH;
        float* Siu = S + 2 * (size_t)NUH;

        gather_kernel<<<ggrid, 256>>>(hu_cur, rout_uu, off + 0 * NN, esrc + 0 * NE, Suu);
        gather_kernel<<<ggrid, 256>>>(hi_cur, rout_iu, off + 2 * NN, esrc + 2 * NE, Siu);
        gather_kernel<<<ggrid, 256>>>(hu_cur, rout_ui, off + 1 * NN, esrc + 1 * NE, Sui);

        // hu_nxt = relu?(Suu@W_uu*rin_uu+b_uu) + relu?(Siu@W_iu*rin_iu+b_iu)
        mma_gemm_kernel<<<grid, 256, TCSMEM>>>(Suu, W[l][0], B[l][0], rin_uu,
                                               hu_nxt, NN, H, relu, 0);
        mma_gemm_kernel<<<grid, 256, TCSMEM>>>(Siu, W[l][2], B[l][2], rin_iu,
                                               hu_nxt, NN, H, relu, 1);
        // hi_nxt = relu?(Sui@W_ui*rin_ui+b_ui)
        mma_gemm_kernel<<<grid, 256, TCSMEM>>>(Sui, W[l][1], B[l][1], rin_ui,
                                               hi_nxt, NN, H, relu, 0);
        cur_pp ^= 1;
    }
    (void)in_sizes; (void)n_in; (void)out_size;
}